// round 6
// baseline (speedup 1.0000x reference)
#include <cuda_runtime.h>
#include <cuda_bf16.h>
#include <cstdint>

// Problem constants
#define BB 2
#define SS 2048
#define EE 1024
#define HH 16
#define DD 64
#define ROWS (BB * SS)        // 4096
#define QKV_N (3 * EE)        // 3072

// Scratch (device globals — no allocation allowed).
__device__ float g_qkv[ROWS * QKV_N];   // [4096, 3072]  (q | k | v per row)
__device__ float g_attn[ROWS * EE];     // [4096, 1024]  attention output

// -------------------------------------------------------------------------
// helpers
// -------------------------------------------------------------------------
__device__ __forceinline__ void cp_async16(void* smem_dst, const void* gmem_src) {
    uint32_t dst = (uint32_t)__cvta_generic_to_shared(smem_dst);
    asm volatile("cp.async.cg.shared.global [%0], [%1], 16;\n"
                 :: "r"(dst), "l"(gmem_src));
}
__device__ __forceinline__ void cp_async_commit() {
    asm volatile("cp.async.commit_group;\n");
}
__device__ __forceinline__ void cp_async_wait_all() {
    asm volatile("cp.async.wait_group 0;\n");
}
__device__ __forceinline__ float ex2(float x) {
    float r;
    asm("ex2.approx.f32 %0, %1;" : "=f"(r) : "f"(x));
    return r;
}

// ---------------------------------------------------------------------------
// SGEMM core, double buffered: C[M,N] = A[M,K] @ B[K,N] + bias[N]
// BM=BN=128, BK=16, 256 threads, 8x8 per thread. M%128==0, N%128==0, K%16==0.
// B tile via cp.async (no transform), A tile via register staging (transpose).
// ---------------------------------------------------------------------------
__device__ __forceinline__ void sgemm_db(
    int N, int K,
    const float* __restrict__ A, const float* __restrict__ B,
    const float* __restrict__ bias, float* __restrict__ C)
{
    __shared__ float As[2][16][128];
    __shared__ float Bs[2][16][128];

    const int tid = threadIdx.x;
    const int bm = blockIdx.y * 128;
    const int bn = blockIdx.x * 128;
    const int tx = tid & 15;          // n direction
    const int ty = tid >> 4;          // m direction

    float acc[8][8];
#pragma unroll
    for (int i = 0; i < 8; i++)
#pragma unroll
        for (int j = 0; j < 8; j++) acc[i][j] = 0.0f;

    // ---- prologue: stage tile 0 into buffer 0 ----
    {
        float4 a0[2];
#pragma unroll
        for (int i = 0; i < 2; i++) {
            int slot = i * 256 + tid;               // [0,512)
            int r  = slot >> 2;
            int c4 = slot & 3;
            a0[i] = *(const float4*)&A[(size_t)(bm + r) * K + c4 * 4];
            int br  = slot >> 5;
            int bc4 = slot & 31;
            cp_async16(&Bs[0][br][bc4 * 4], &B[(size_t)br * N + bn + bc4 * 4]);
        }
        cp_async_commit();
#pragma unroll
        for (int i = 0; i < 2; i++) {
            int slot = i * 256 + tid;
            int r  = slot >> 2;
            int c4 = slot & 3;
            As[0][c4 * 4 + 0][r] = a0[i].x;
            As[0][c4 * 4 + 1][r] = a0[i].y;
            As[0][c4 * 4 + 2][r] = a0[i].z;
            As[0][c4 * 4 + 3][r] = a0[i].w;
        }
        cp_async_wait_all();
        __syncthreads();
    }

    const int NT = K / 16;
    for (int it = 0; it < NT; it++) {
        const int cur = it & 1;
        float4 an[2];
        if (it + 1 < NT) {
            const int k0 = (it + 1) * 16;
#pragma unroll
            for (int i = 0; i < 2; i++) {
                int slot = i * 256 + tid;
                int r  = slot >> 2;
                int c4 = slot & 3;
                an[i] = *(const float4*)&A[(size_t)(bm + r) * K + k0 + c4 * 4];
                int br  = slot >> 5;
                int bc4 = slot & 31;
                cp_async16(&Bs[cur ^ 1][br][bc4 * 4],
                           &B[(size_t)(k0 + br) * N + bn + bc4 * 4]);
            }
            cp_async_commit();
        }

        // ---- compute on current buffer ----
#pragma unroll
        for (int kk = 0; kk < 16; kk++) {
            float ra[8], rb[8];
            *(float4*)&ra[0] = *(const float4*)&As[cur][kk][ty * 8];
            *(float4*)&ra[4] = *(const float4*)&As[cur][kk][ty * 8 + 4];
            *(float4*)&rb[0] = *(const float4*)&Bs[cur][kk][tx * 8];
            *(float4*)&rb[4] = *(const float4*)&Bs[cur][kk][tx * 8 + 4];
#pragma unroll
            for (int i = 0; i < 8; i++)
#pragma unroll
                for (int j = 0; j < 8; j++)
                    acc[i][j] += ra[i] * rb[j];
        }

        if (it + 1 < NT) {
#pragma unroll
            for (int i = 0; i < 2; i++) {
                int slot = i * 256 + tid;
                int r  = slot >> 2;
                int c4 = slot & 3;
                As[cur ^ 1][c4 * 4 + 0][r] = an[i].x;
                As[cur ^ 1][c4 * 4 + 1][r] = an[i].y;
                As[cur ^ 1][c4 * 4 + 2][r] = an[i].z;
                As[cur ^ 1][c4 * 4 + 3][r] = an[i].w;
            }
            cp_async_wait_all();
            __syncthreads();
        }
    }

    // ---- epilogue: bias + store ----
#pragma unroll
    for (int i = 0; i < 8; i++) {
        int row = bm + ty * 8 + i;
        float* Crow = &C[(size_t)row * N + bn];
#pragma unroll
        for (int j = 0; j < 8; j += 4) {
            float4 o;
            int n = tx * 8 + j;
            o.x = acc[i][j + 0] + bias[bn + n + 0];
            o.y = acc[i][j + 1] + bias[bn + n + 1];
            o.z = acc[i][j + 2] + bias[bn + n + 2];
            o.w = acc[i][j + 3] + bias[bn + n + 3];
            *(float4*)&Crow[n] = o;
        }
    }
}

// GEMM 1: g_qkv = x @ Wqkv + bqkv   [4096,1024]@[1024,3072]
__global__ __launch_bounds__(256, 2) void qkv_gemm(
    const float* __restrict__ x, const float* __restrict__ Wqkv,
    const float* __restrict__ bqkv)
{
    sgemm_db(QKV_N, EE, x, Wqkv, bqkv, g_qkv);
}

// GEMM 2: out = g_attn @ Wout + bout   [4096,1024]@[1024,1024]
__global__ __launch_bounds__(256, 2) void out_gemm(
    const float* __restrict__ Wout, const float* __restrict__ bout,
    float* __restrict__ out)
{
    sgemm_db(EE, EE, g_attn, Wout, bout, out);
}

// ---------------------------------------------------------------------------
// Flash attention (fp32 SIMT), branchless chunked online softmax.
// grid (S/128 qtiles, B*H), 128 threads; thread t owns query row qtile*128+t.
// q (64 regs, pre-scaled by 0.125*log2e) and O (64 regs) in registers.
// K/V tiles of 64 rows staged in shared via cp.async; scores in log2 domain.
// Per 8-key chunk: 8 dots -> chunk max -> always-rescale by alpha (branch-free).
// ---------------------------------------------------------------------------
__global__ __launch_bounds__(128, 3) void flash_attn(const int* __restrict__ mask)
{
    __shared__ float Ks[64][64];
    __shared__ float Vs[64][64];
    __shared__ float msk[64];

    const int t  = threadIdx.x;
    const int b  = blockIdx.y / HH;
    const int h  = blockIdx.y % HH;
    const int qi = blockIdx.x * 128 + t;

    // q pre-scaled by (1/sqrt(D)) * log2(e) so scores are base-2 logits
    const float QSCALE = 0.125f * 1.4426950408889634f;
    float4 q4[16];
    {
        const float4* qsrc =
            (const float4*)&g_qkv[(size_t)(b * SS + qi) * QKV_N + h * DD];
#pragma unroll
        for (int i = 0; i < 16; i++) {
            float4 v = qsrc[i];
            v.x *= QSCALE; v.y *= QSCALE; v.z *= QSCALE; v.w *= QSCALE;
            q4[i] = v;
        }
    }

    float4 O4[16];
#pragma unroll
    for (int i = 0; i < 16; i++) O4[i] = make_float4(0.f, 0.f, 0.f, 0.f);
    float m = -1e30f;
    float l = 0.0f;

    for (int kt = 0; kt < SS / 64; kt++) {
        // cp.async fill of K and V tiles (64 rows x 64 floats each)
#pragma unroll
        for (int i = 0; i < 8; i++) {
            int slot = i * 128 + t;            // [0,1024) float4 slots
            int rr = slot >> 4;
            int c4 = slot & 15;
            size_t base = (size_t)(b * SS + kt * 64 + rr) * QKV_N + h * DD;
            cp_async16(&Ks[rr][c4 * 4], &g_qkv[base + EE + c4 * 4]);
            cp_async16(&Vs[rr][c4 * 4], &g_qkv[base + 2 * EE + c4 * 4]);
        }
        cp_async_commit();
        if (t < 64)
            msk[t] = (mask[b * SS + kt * 64 + t] == 0) ? -1e30f : 0.0f;
        cp_async_wait_all();
        __syncthreads();

#pragma unroll
        for (int c = 0; c < 8; c++) {
            // --- 8 dot products (base-2 logits) ---
            float s[8];
#pragma unroll
            for (int j = 0; j < 8; j++) {
                const float4* Krow = (const float4*)&Ks[c * 8 + j][0];
                float a0 = 0.f, a1 = 0.f, a2 = 0.f, a3 = 0.f;
#pragma unroll
                for (int i = 0; i < 16; i++) {
                    float4 kv = Krow[i];
                    a0 += q4[i].x * kv.x;
                    a1 += q4[i].y * kv.y;
                    a2 += q4[i].z * kv.z;
                    a3 += q4[i].w * kv.w;
                }
                s[j] = (a0 + a1) + (a2 + a3) + msk[c * 8 + j];
            }

            // --- branchless online-softmax update ---
            float cmax = fmaxf(fmaxf(fmaxf(s[0], s[1]), fmaxf(s[2], s[3])),
                               fmaxf(fmaxf(s[4], s[5]), fmaxf(s[6], s[7])));
            float mnew  = fmaxf(m, cmax);
            float alpha = ex2(m - mnew);     // == 1.0 when no new max
            m = mnew;

            float p[8];
            float psum = 0.f;
#pragma unroll
            for (int j = 0; j < 8; j++) {
                p[j] = ex2(s[j] - mnew);
                psum += p[j];
            }
            l = l * alpha + psum;

            // --- PV accumulation: O = O*alpha + sum_j p_j * V_j ---
#pragma unroll
            for (int i = 0; i < 16; i++) {
                float4 o = O4[i];
                o.x *= alpha; o.y *= alpha; o.z *= alpha; o.w *= alpha;
#pragma unroll
                for (int j = 0; j < 8; j++) {
                    float4 vv = *(const float4*)&Vs[c * 8 + j][i * 4];
                    o.x += p[j] * vv.x;
                    o.y += p[j] * vv.y;
                    o.z += p[j] * vv.z;
                    o.w += p[j] * vv.w;
                }
                O4[i] = o;
            }
        }
        __syncthreads();
    }

    float inv = 1.0f / l;
    float4* dst = (float4*)&g_attn[(size_t)(b * SS + qi) * EE + h * DD];
#pragma unroll
    for (int i = 0; i < 16; i++) {
        float4 o = O4[i];
        o.x *= inv; o.y *= inv; o.z *= inv; o.w *= inv;
        dst[i] = o;
    }
}

// ---------------------------------------------------------------------------
// Launch — pure kernel launches only (graph-capture safe).
// inputs: x[B,S,E] f32, mask[B,S] i32, Wqkv[E,3E] f32, bqkv[3E] f32,
//         Wout[E,E] f32, bout[E] f32. output: [B,S,E] f32.
// ---------------------------------------------------------------------------
extern "C" void kernel_launch(void* const* d_in, const int* in_sizes, int n_in,
                              void* d_out, int out_size)
{
    const float* x    = (const float*)d_in[0];
    const int*   mask = (const int*)d_in[1];
    const float* Wqkv = (const float*)d_in[2];
    const float* bqkv = (const float*)d_in[3];
    const float* Wout = (const float*)d_in[4];
    const float* bout = (const float*)d_in[5];
    float* out = (float*)d_out;

    {   // 1) qkv = x @ Wqkv + bqkv
        dim3 grid(QKV_N / 128, ROWS / 128);
        qkv_gemm<<<grid, 256>>>(x, Wqkv, bqkv);
    }
    {   // 2) attention -> g_attn
        dim3 grid(SS / 128, BB * HH);
        flash_attn<<<grid, 128>>>(mask);
    }
    {   // 3) out = g_attn @ Wout + bout
        dim3 grid(EE / 128, ROWS / 128);
        out_gemm<<<grid, 256>>>(Wout, bout, out);
    }
}

// round 7
// speedup vs baseline: 1.0360x; 1.0360x over previous
#include <cuda_runtime.h>
#include <cuda_bf16.h>
#include <cstdint>

// Problem constants
#define BB 2
#define SS 2048
#define EE 1024
#define HH 16
#define DD 64
#define ROWS (BB * SS)        // 4096
#define QKV_N (3 * EE)        // 3072

// Scratch (device globals — no allocation allowed).
__device__ float g_qkv[ROWS * QKV_N];   // [4096, 3072]  (q | k | v per row)
__device__ float g_attn[ROWS * EE];     // [4096, 1024]  attention output

// -------------------------------------------------------------------------
// helpers
// -------------------------------------------------------------------------
__device__ __forceinline__ void cp_async16(void* smem_dst, const void* gmem_src) {
    uint32_t dst = (uint32_t)__cvta_generic_to_shared(smem_dst);
    asm volatile("cp.async.cg.shared.global [%0], [%1], 16;\n"
                 :: "r"(dst), "l"(gmem_src));
}
__device__ __forceinline__ void cp_async_commit() {
    asm volatile("cp.async.commit_group;\n");
}
__device__ __forceinline__ void cp_async_wait_all() {
    asm volatile("cp.async.wait_group 0;\n");
}
__device__ __forceinline__ float ex2(float x) {
    float r;
    asm("ex2.approx.f32 %0, %1;" : "=f"(r) : "f"(x));
    return r;
}

// ---------------------------------------------------------------------------
// SGEMM core, double buffered: C[M,N] = A[M,K] @ B[K,N] + bias[N]
// BM=BN=128, BK=16, 256 threads, 8x8 per thread. M%128==0, N%128==0, K%16==0.
// B tile via cp.async (no transform), A tile via register staging (transpose).
// ---------------------------------------------------------------------------
__device__ __forceinline__ void sgemm_db(
    int N, int K,
    const float* __restrict__ A, const float* __restrict__ B,
    const float* __restrict__ bias, float* __restrict__ C)
{
    __shared__ float As[2][16][128];
    __shared__ float Bs[2][16][128];

    const int tid = threadIdx.x;
    const int bm = blockIdx.y * 128;
    const int bn = blockIdx.x * 128;
    const int tx = tid & 15;          // n direction
    const int ty = tid >> 4;          // m direction

    float acc[8][8];
#pragma unroll
    for (int i = 0; i < 8; i++)
#pragma unroll
        for (int j = 0; j < 8; j++) acc[i][j] = 0.0f;

    // ---- prologue: stage tile 0 into buffer 0 ----
    {
        float4 a0[2];
#pragma unroll
        for (int i = 0; i < 2; i++) {
            int slot = i * 256 + tid;               // [0,512)
            int r  = slot >> 2;
            int c4 = slot & 3;
            a0[i] = *(const float4*)&A[(size_t)(bm + r) * K + c4 * 4];
            int br  = slot >> 5;
            int bc4 = slot & 31;
            cp_async16(&Bs[0][br][bc4 * 4], &B[(size_t)br * N + bn + bc4 * 4]);
        }
        cp_async_commit();
#pragma unroll
        for (int i = 0; i < 2; i++) {
            int slot = i * 256 + tid;
            int r  = slot >> 2;
            int c4 = slot & 3;
            As[0][c4 * 4 + 0][r] = a0[i].x;
            As[0][c4 * 4 + 1][r] = a0[i].y;
            As[0][c4 * 4 + 2][r] = a0[i].z;
            As[0][c4 * 4 + 3][r] = a0[i].w;
        }
        cp_async_wait_all();
        __syncthreads();
    }

    const int NT = K / 16;
    for (int it = 0; it < NT; it++) {
        const int cur = it & 1;
        float4 an[2];
        if (it + 1 < NT) {
            const int k0 = (it + 1) * 16;
#pragma unroll
            for (int i = 0; i < 2; i++) {
                int slot = i * 256 + tid;
                int r  = slot >> 2;
                int c4 = slot & 3;
                an[i] = *(const float4*)&A[(size_t)(bm + r) * K + k0 + c4 * 4];
                int br  = slot >> 5;
                int bc4 = slot & 31;
                cp_async16(&Bs[cur ^ 1][br][bc4 * 4],
                           &B[(size_t)(k0 + br) * N + bn + bc4 * 4]);
            }
            cp_async_commit();
        }

        // ---- compute on current buffer ----
#pragma unroll
        for (int kk = 0; kk < 16; kk++) {
            float ra[8], rb[8];
            *(float4*)&ra[0] = *(const float4*)&As[cur][kk][ty * 8];
            *(float4*)&ra[4] = *(const float4*)&As[cur][kk][ty * 8 + 4];
            *(float4*)&rb[0] = *(const float4*)&Bs[cur][kk][tx * 8];
            *(float4*)&rb[4] = *(const float4*)&Bs[cur][kk][tx * 8 + 4];
#pragma unroll
            for (int i = 0; i < 8; i++)
#pragma unroll
                for (int j = 0; j < 8; j++)
                    acc[i][j] += ra[i] * rb[j];
        }

        if (it + 1 < NT) {
#pragma unroll
            for (int i = 0; i < 2; i++) {
                int slot = i * 256 + tid;
                int r  = slot >> 2;
                int c4 = slot & 3;
                As[cur ^ 1][c4 * 4 + 0][r] = an[i].x;
                As[cur ^ 1][c4 * 4 + 1][r] = an[i].y;
                As[cur ^ 1][c4 * 4 + 2][r] = an[i].z;
                As[cur ^ 1][c4 * 4 + 3][r] = an[i].w;
            }
            cp_async_wait_all();
            __syncthreads();
        }
    }

    // ---- epilogue: bias + store ----
#pragma unroll
    for (int i = 0; i < 8; i++) {
        int row = bm + ty * 8 + i;
        float* Crow = &C[(size_t)row * N + bn];
#pragma unroll
        for (int j = 0; j < 8; j += 4) {
            float4 o;
            int n = tx * 8 + j;
            o.x = acc[i][j + 0] + bias[bn + n + 0];
            o.y = acc[i][j + 1] + bias[bn + n + 1];
            o.z = acc[i][j + 2] + bias[bn + n + 2];
            o.w = acc[i][j + 3] + bias[bn + n + 3];
            *(float4*)&Crow[n] = o;
        }
    }
}

// GEMM 1: g_qkv = x @ Wqkv + bqkv   [4096,1024]@[1024,3072]
__global__ __launch_bounds__(256, 2) void qkv_gemm(
    const float* __restrict__ x, const float* __restrict__ Wqkv,
    const float* __restrict__ bqkv)
{
    sgemm_db(QKV_N, EE, x, Wqkv, bqkv, g_qkv);
}

// GEMM 2: out = g_attn @ Wout + bout   [4096,1024]@[1024,1024]
__global__ __launch_bounds__(256, 2) void out_gemm(
    const float* __restrict__ Wout, const float* __restrict__ bout,
    float* __restrict__ out)
{
    sgemm_db(EE, EE, g_attn, Wout, bout, out);
}

// ---------------------------------------------------------------------------
// Flash attention (fp32 SIMT), branchless chunked online softmax.
// grid (S/128 qtiles, B*H), 128 threads; thread t owns query row qtile*128+t.
// q (64 regs, pre-scaled by 0.125*log2e) and O (64 regs) in registers.
// __launch_bounds__(128, 2): 256-reg budget -> NO SPILLS, 8 warps/SM
// (2 warps/SMSP, enough to saturate the FMA pipe at rt=2).
// Per 8-key chunk: 8 dots -> chunk max -> always-rescale by alpha (branch-free).
// ---------------------------------------------------------------------------
__global__ __launch_bounds__(128, 2) void flash_attn(const int* __restrict__ mask)
{
    __shared__ float Ks[64][64];
    __shared__ float Vs[64][64];
    __shared__ float msk[64];

    const int t  = threadIdx.x;
    const int b  = blockIdx.y / HH;
    const int h  = blockIdx.y % HH;
    const int qi = blockIdx.x * 128 + t;

    // q pre-scaled by (1/sqrt(D)) * log2(e) so scores are base-2 logits
    const float QSCALE = 0.125f * 1.4426950408889634f;
    float4 q4[16];
    {
        const float4* qsrc =
            (const float4*)&g_qkv[(size_t)(b * SS + qi) * QKV_N + h * DD];
#pragma unroll
        for (int i = 0; i < 16; i++) {
            float4 v = qsrc[i];
            v.x *= QSCALE; v.y *= QSCALE; v.z *= QSCALE; v.w *= QSCALE;
            q4[i] = v;
        }
    }

    float4 O4[16];
#pragma unroll
    for (int i = 0; i < 16; i++) O4[i] = make_float4(0.f, 0.f, 0.f, 0.f);
    float m = -1e30f;
    float l = 0.0f;

    for (int kt = 0; kt < SS / 64; kt++) {
        // cp.async fill of K and V tiles (64 rows x 64 floats each)
#pragma unroll
        for (int i = 0; i < 8; i++) {
            int slot = i * 128 + t;            // [0,1024) float4 slots
            int rr = slot >> 4;
            int c4 = slot & 15;
            size_t base = (size_t)(b * SS + kt * 64 + rr) * QKV_N + h * DD;
            cp_async16(&Ks[rr][c4 * 4], &g_qkv[base + EE + c4 * 4]);
            cp_async16(&Vs[rr][c4 * 4], &g_qkv[base + 2 * EE + c4 * 4]);
        }
        cp_async_commit();
        if (t < 64)
            msk[t] = (mask[b * SS + kt * 64 + t] == 0) ? -1e30f : 0.0f;
        cp_async_wait_all();
        __syncthreads();

#pragma unroll
        for (int c = 0; c < 8; c++) {
            // --- 8 dot products (base-2 logits) ---
            float s[8];
#pragma unroll
            for (int j = 0; j < 8; j++) {
                const float4* Krow = (const float4*)&Ks[c * 8 + j][0];
                float a0 = 0.f, a1 = 0.f, a2 = 0.f, a3 = 0.f;
#pragma unroll
                for (int i = 0; i < 16; i++) {
                    float4 kv = Krow[i];
                    a0 += q4[i].x * kv.x;
                    a1 += q4[i].y * kv.y;
                    a2 += q4[i].z * kv.z;
                    a3 += q4[i].w * kv.w;
                }
                s[j] = (a0 + a1) + (a2 + a3) + msk[c * 8 + j];
            }

            // --- branchless online-softmax update ---
            float cmax = fmaxf(fmaxf(fmaxf(s[0], s[1]), fmaxf(s[2], s[3])),
                               fmaxf(fmaxf(s[4], s[5]), fmaxf(s[6], s[7])));
            float mnew  = fmaxf(m, cmax);
            float alpha = ex2(m - mnew);     // == 1.0 when no new max
            m = mnew;

            float psum = 0.f;
#pragma unroll
            for (int j = 0; j < 8; j++) {
                s[j] = ex2(s[j] - mnew);     // reuse s[] as p[]
                psum += s[j];
            }
            l = l * alpha + psum;

            // --- PV accumulation: O = O*alpha + sum_j p_j * V_j ---
#pragma unroll
            for (int i = 0; i < 16; i++) {
                float4 o = O4[i];
                o.x *= alpha; o.y *= alpha; o.z *= alpha; o.w *= alpha;
#pragma unroll
                for (int j = 0; j < 8; j++) {
                    float4 vv = *(const float4*)&Vs[c * 8 + j][i * 4];
                    o.x += s[j] * vv.x;
                    o.y += s[j] * vv.y;
                    o.z += s[j] * vv.z;
                    o.w += s[j] * vv.w;
                }
                O4[i] = o;
            }
        }
        __syncthreads();
    }

    float inv = 1.0f / l;
    float4* dst = (float4*)&g_attn[(size_t)(b * SS + qi) * EE + h * DD];
#pragma unroll
    for (int i = 0; i < 16; i++) {
        float4 o = O4[i];
        o.x *= inv; o.y *= inv; o.z *= inv; o.w *= inv;
        dst[i] = o;
    }
}

// ---------------------------------------------------------------------------
// Launch — pure kernel launches only (graph-capture safe).
// inputs: x[B,S,E] f32, mask[B,S] i32, Wqkv[E,3E] f32, bqkv[3E] f32,
//         Wout[E,E] f32, bout[E] f32. output: [B,S,E] f32.
// ---------------------------------------------------------------------------
extern "C" void kernel_launch(void* const* d_in, const int* in_sizes, int n_in,
                              void* d_out, int out_size)
{
    const float* x    = (const float*)d_in[0];
    const int*   mask = (const int*)d_in[1];
    const float* Wqkv = (const float*)d_in[2];
    const float* bqkv = (const float*)d_in[3];
    const float* Wout = (const float*)d_in[4];
    const float* bout = (const float*)d_in[5];
    float* out = (float*)d_out;

    {   // 1) qkv = x @ Wqkv + bqkv
        dim3 grid(QKV_N / 128, ROWS / 128);
        qkv_gemm<<<grid, 256>>>(x, Wqkv, bqkv);
    }
    {   // 2) attention -> g_attn
        dim3 grid(SS / 128, BB * HH);
        flash_attn<<<grid, 128>>>(mask);
    }
    {   // 3) out = g_attn @ Wout + bout
        dim3 grid(EE / 128, ROWS / 128);
        out_gemm<<<grid, 256>>>(Wout, bout, out);
    }
}

// round 8
// speedup vs baseline: 1.7328x; 1.6725x over previous
#include <cuda_runtime.h>
#include <cuda_bf16.h>
#include <cstdint>

// Problem constants
#define BB 2
#define SS 2048
#define EE 1024
#define HH 16
#define DD 64
#define ROWS (BB * SS)        // 4096
#define QKV_N (3 * EE)        // 3072

// Scratch (device globals — no allocation allowed).
__device__ float g_qkv[ROWS * QKV_N];   // [4096, 3072]  (q | k | v per row)
__device__ float g_attn[ROWS * EE];     // [4096, 1024]  attention output

// -------------------------------------------------------------------------
// helpers
// -------------------------------------------------------------------------
__device__ __forceinline__ uint32_t f2tf32(float x) {
    uint32_t r;
    asm("cvt.rna.tf32.f32 %0, %1;" : "=r"(r) : "f"(x));
    return r;
}

// mma.sync m16n8k8 tf32: D = A(16x8,row) * B(8x8,col-frag) + D
__device__ __forceinline__ void mma_tf32(float c[4], const uint32_t a[4],
                                         const uint32_t b[2]) {
    asm volatile(
        "mma.sync.aligned.m16n8k8.row.col.f32.tf32.tf32.f32 "
        "{%0,%1,%2,%3}, {%4,%5,%6,%7}, {%8,%9}, {%0,%1,%2,%3};"
        : "+f"(c[0]), "+f"(c[1]), "+f"(c[2]), "+f"(c[3])
        : "r"(a[0]), "r"(a[1]), "r"(a[2]), "r"(a[3]),
          "r"(b[0]), "r"(b[1]));
}

// ---------------------------------------------------------------------------
// TF32 tensor-core GEMM: C[M,N] = A[M,K] @ B[K,N] + bias[N]
// BM=BN=128, BK=32, 256 threads = 8 warps (4 m x 2 n), warp tile 32x64.
// K = 1024 fixed (both GEMMs). Single smem buffer, register-staged prefetch.
// Smem padded so all fragment LDS are bank-conflict-free:
//   As stride 36 (36 mod 32 = 4), Bs stride 136 (136 mod 32 = 8).
// ---------------------------------------------------------------------------
#define GK 1024
#define GNT (GK / 32)   // 32 K-iterations

__device__ __forceinline__ void tf32_gemm_body(
    int N,
    const float* __restrict__ A, const float* __restrict__ B,
    const float* __restrict__ bias, float* __restrict__ C)
{
    __shared__ uint32_t As[128][36];   // [m][k], BK=32 + pad 4
    __shared__ uint32_t Bs[32][136];   // [k][n], BN=128 + pad 8

    const int tid  = threadIdx.x;
    const int lane = tid & 31;
    const int wid  = tid >> 5;
    const int g    = lane >> 2;      // groupID (0..7)
    const int t    = lane & 3;       // threadID_in_group (0..3)
    const int wm   = wid >> 1;       // warp m index (0..3)
    const int wn   = wid & 1;        // warp n index (0..1)

    const int bm = blockIdx.y * 128;
    const int bn = blockIdx.x * 128;

    float acc[2][8][4];
#pragma unroll
    for (int mt = 0; mt < 2; mt++)
#pragma unroll
        for (int nt = 0; nt < 8; nt++)
#pragma unroll
            for (int r = 0; r < 4; r++) acc[mt][nt][r] = 0.0f;

    // Per-thread staging: A tile 128x32 = 1024 float4 -> 4/thread,
    //                     B tile  32x128 = 1024 float4 -> 4/thread.
    float4 sa[4], sb[4];

    // ---- prologue: load tile 0 ----
#pragma unroll
    for (int i = 0; i < 4; i++) {
        int slot = i * 256 + tid;            // [0,1024)
        int ar = slot >> 3, ac4 = slot & 7;  // A: row, float4-col
        sa[i] = *(const float4*)&A[(size_t)(bm + ar) * GK + ac4 * 4];
        int br = slot >> 5, bc4 = slot & 31; // B: row, float4-col
        sb[i] = *(const float4*)&B[(size_t)br * N + bn + bc4 * 4];
    }

    for (int it = 0; it < GNT; it++) {
        // ---- store staged tile to smem (with tf32 rounding) ----
#pragma unroll
        for (int i = 0; i < 4; i++) {
            int slot = i * 256 + tid;
            int ar = slot >> 3, ac4 = slot & 7;
            uint4 av = make_uint4(f2tf32(sa[i].x), f2tf32(sa[i].y),
                                  f2tf32(sa[i].z), f2tf32(sa[i].w));
            *(uint4*)&As[ar][ac4 * 4] = av;
            int br = slot >> 5, bc4 = slot & 31;
            uint4 bv = make_uint4(f2tf32(sb[i].x), f2tf32(sb[i].y),
                                  f2tf32(sb[i].z), f2tf32(sb[i].w));
            *(uint4*)&Bs[br][bc4 * 4] = bv;
        }
        __syncthreads();

        // ---- prefetch next tile into registers (overlaps MMA compute) ----
        if (it + 1 < GNT) {
            const int k0 = (it + 1) * 32;
#pragma unroll
            for (int i = 0; i < 4; i++) {
                int slot = i * 256 + tid;
                int ar = slot >> 3, ac4 = slot & 7;
                sa[i] = *(const float4*)&A[(size_t)(bm + ar) * GK + k0 + ac4 * 4];
                int br = slot >> 5, bc4 = slot & 31;
                sb[i] = *(const float4*)&B[(size_t)(k0 + br) * N + bn + bc4 * 4];
            }
        }

        // ---- MMA compute: 4 k-steps of 8 ----
#pragma unroll
        for (int ks = 0; ks < 4; ks++) {
            const int kb = ks * 8;
            uint32_t af[2][4];
#pragma unroll
            for (int mt = 0; mt < 2; mt++) {
                const int mb = wm * 32 + mt * 16;
                af[mt][0] = As[mb + g    ][kb + t    ];
                af[mt][1] = As[mb + g + 8][kb + t    ];
                af[mt][2] = As[mb + g    ][kb + t + 4];
                af[mt][3] = As[mb + g + 8][kb + t + 4];
            }
            uint32_t bf[8][2];
#pragma unroll
            for (int nt = 0; nt < 8; nt++) {
                const int nb = wn * 64 + nt * 8 + g;
                bf[nt][0] = Bs[kb + t    ][nb];
                bf[nt][1] = Bs[kb + t + 4][nb];
            }
#pragma unroll
            for (int mt = 0; mt < 2; mt++)
#pragma unroll
                for (int nt = 0; nt < 8; nt++)
                    mma_tf32(acc[mt][nt], af[mt], bf[nt]);
        }
        __syncthreads();
    }

    // ---- epilogue: bias + store ----
#pragma unroll
    for (int mt = 0; mt < 2; mt++) {
        const int row0 = bm + wm * 32 + mt * 16 + g;
#pragma unroll
        for (int nt = 0; nt < 8; nt++) {
            const int col = bn + wn * 64 + nt * 8 + 2 * t;
            const float b0 = bias[col], b1 = bias[col + 1];
            float2 v0 = make_float2(acc[mt][nt][0] + b0, acc[mt][nt][1] + b1);
            float2 v1 = make_float2(acc[mt][nt][2] + b0, acc[mt][nt][3] + b1);
            *(float2*)&C[(size_t)row0 * N + col]       = v0;
            *(float2*)&C[(size_t)(row0 + 8) * N + col] = v1;
        }
    }
}

// GEMM 1: g_qkv = x @ Wqkv + bqkv   [4096,1024]@[1024,3072]
__global__ __launch_bounds__(256) void qkv_gemm(
    const float* __restrict__ x, const float* __restrict__ Wqkv,
    const float* __restrict__ bqkv)
{
    tf32_gemm_body(QKV_N, x, Wqkv, bqkv, g_qkv);
}

// GEMM 2: out = g_attn @ Wout + bout   [4096,1024]@[1024,1024]
__global__ __launch_bounds__(256) void out_gemm(
    const float* __restrict__ Wout, const float* __restrict__ bout,
    float* __restrict__ out)
{
    tf32_gemm_body(EE, g_attn, Wout, bout, out);
}

// ---------------------------------------------------------------------------
// Flash attention (fp32 SIMT) — EXACT round-5 structure (proven ~1500us).
// grid (S/128 qtiles, B*H), 128 threads; thread t owns one query row.
// ---------------------------------------------------------------------------
__global__ __launch_bounds__(128) void flash_attn(const int* __restrict__ mask)
{
    __shared__ float Ks[64][64];
    __shared__ float Vs[64][64];
    __shared__ float msk[64];

    const int t  = threadIdx.x;
    const int b  = blockIdx.y / HH;
    const int h  = blockIdx.y % HH;
    const int qi = blockIdx.x * 128 + t;

    // Load q row, pre-scaled by 1/sqrt(D) = 0.125
    float4 q4[16];
    {
        const float4* qsrc =
            (const float4*)&g_qkv[(size_t)(b * SS + qi) * QKV_N + h * DD];
#pragma unroll
        for (int i = 0; i < 16; i++) {
            float4 v = qsrc[i];
            v.x *= 0.125f; v.y *= 0.125f; v.z *= 0.125f; v.w *= 0.125f;
            q4[i] = v;
        }
    }

    float4 O4[16];
#pragma unroll
    for (int i = 0; i < 16; i++) O4[i] = make_float4(0.f, 0.f, 0.f, 0.f);
    float m = -1e30f;
    float l = 0.0f;

    for (int kt = 0; kt < SS / 64; kt++) {
#pragma unroll
        for (int i = 0; i < 8; i++) {
            int slot = i * 128 + t;            // [0,1024) float4 slots
            int rr = slot >> 4;
            int c4 = slot & 15;
            size_t base = (size_t)(b * SS + kt * 64 + rr) * QKV_N + h * DD;
            ((float4*)&Ks[rr][0])[c4] = *(const float4*)&g_qkv[base + EE + c4 * 4];
            ((float4*)&Vs[rr][0])[c4] = *(const float4*)&g_qkv[base + 2 * EE + c4 * 4];
        }
        if (t < 64)
            msk[t] = (mask[b * SS + kt * 64 + t] == 0) ? -1e30f : 0.0f;
        __syncthreads();

        for (int kk = 0; kk < 64; kk++) {
            const float4* Krow = (const float4*)&Ks[kk][0];
            float a0 = 0.f, a1 = 0.f, a2 = 0.f, a3 = 0.f;
#pragma unroll
            for (int i = 0; i < 16; i++) {
                float4 kv = Krow[i];
                a0 += q4[i].x * kv.x;
                a1 += q4[i].y * kv.y;
                a2 += q4[i].z * kv.z;
                a3 += q4[i].w * kv.w;
            }
            float s = (a0 + a1) + (a2 + a3) + msk[kk];

            const float4* Vrow = (const float4*)&Vs[kk][0];
            if (s <= m) {
                float p = __expf(s - m);
                l += p;
#pragma unroll
                for (int i = 0; i < 16; i++) {
                    float4 vv = Vrow[i];
                    O4[i].x += p * vv.x;
                    O4[i].y += p * vv.y;
                    O4[i].z += p * vv.z;
                    O4[i].w += p * vv.w;
                }
            } else {
                float alpha = __expf(m - s);
                m = s;
                l = l * alpha + 1.0f;
#pragma unroll
                for (int i = 0; i < 16; i++) {
                    float4 vv = Vrow[i];
                    O4[i].x = O4[i].x * alpha + vv.x;
                    O4[i].y = O4[i].y * alpha + vv.y;
                    O4[i].z = O4[i].z * alpha + vv.z;
                    O4[i].w = O4[i].w * alpha + vv.w;
                }
            }
        }
        __syncthreads();
    }

    float inv = 1.0f / l;
    float4* dst = (float4*)&g_attn[(size_t)(b * SS + qi) * EE + h * DD];
#pragma unroll
    for (int i = 0; i < 16; i++) {
        float4 o = O4[i];
        o.x *= inv; o.y *= inv; o.z *= inv; o.w *= inv;
        dst[i] = o;
    }
}

// ---------------------------------------------------------------------------
// Launch — pure kernel launches only (graph-capture safe).
// inputs: x[B,S,E] f32, mask[B,S] i32, Wqkv[E,3E] f32, bqkv[3E] f32,
//         Wout[E,E] f32, bout[E] f32. output: [B,S,E] f32.
// ---------------------------------------------------------------------------
extern "C" void kernel_launch(void* const* d_in, const int* in_sizes, int n_in,
                              void* d_out, int out_size)
{
    const float* x    = (const float*)d_in[0];
    const int*   mask = (const int*)d_in[1];
    const float* Wqkv = (const float*)d_in[2];
    const float* bqkv = (const float*)d_in[3];
    const float* Wout = (const float*)d_in[4];
    const float* bout = (const float*)d_in[5];
    float* out = (float*)d_out;

    {   // 1) qkv = x @ Wqkv + bqkv
        dim3 grid(QKV_N / 128, ROWS / 128);
        qkv_gemm<<<grid, 256>>>(x, Wqkv, bqkv);
    }
    {   // 2) attention -> g_attn
        dim3 grid(SS / 128, BB * HH);
        flash_attn<<<grid, 128>>>(mask);
    }
    {   // 3) out = g_attn @ Wout + bout
        dim3 grid(EE / 128, ROWS / 128);
        out_gemm<<<grid, 256>>>(Wout, bout, out);
    }
}

// round 9
// speedup vs baseline: 4.6957x; 2.7099x over previous
#include <cuda_runtime.h>
#include <cuda_bf16.h>
#include <cstdint>

// Problem constants
#define BB 2
#define SS 2048
#define EE 1024
#define HH 16
#define DD 64
#define ROWS (BB * SS)        // 4096
#define QKV_N (3 * EE)        // 3072

// Scratch (device globals — no allocation allowed).
__device__ float g_qkv[ROWS * QKV_N];   // [4096, 3072]  (q | k | v per row)
__device__ float g_attn[ROWS * EE];     // [4096, 1024]  attention output

// -------------------------------------------------------------------------
// helpers
// -------------------------------------------------------------------------
__device__ __forceinline__ uint32_t f2tf32(float x) {
    uint32_t r;
    asm("cvt.rna.tf32.f32 %0, %1;" : "=r"(r) : "f"(x));
    return r;
}
__device__ __forceinline__ float ex2(float x) {
    float r;
    asm("ex2.approx.f32 %0, %1;" : "=f"(r) : "f"(x));
    return r;
}

// mma.sync m16n8k8 tf32: D = A(16x8,row) * B(8x8,col-frag) + D
__device__ __forceinline__ void mma_tf32(float c[4], const uint32_t a[4],
                                         const uint32_t b[2]) {
    asm volatile(
        "mma.sync.aligned.m16n8k8.row.col.f32.tf32.tf32.f32 "
        "{%0,%1,%2,%3}, {%4,%5,%6,%7}, {%8,%9}, {%0,%1,%2,%3};"
        : "+f"(c[0]), "+f"(c[1]), "+f"(c[2]), "+f"(c[3])
        : "r"(a[0]), "r"(a[1]), "r"(a[2]), "r"(a[3]),
          "r"(b[0]), "r"(b[1]));
}

// ---------------------------------------------------------------------------
// TF32 tensor-core GEMM: C[M,N] = A[M,K] @ B[K,N] + bias[N]   (round-8, proven)
// BM=BN=128, BK=32, 256 threads = 8 warps (4 m x 2 n), warp tile 32x64.
// ---------------------------------------------------------------------------
#define GK 1024
#define GNT (GK / 32)   // 32 K-iterations

__device__ __forceinline__ void tf32_gemm_body(
    int N,
    const float* __restrict__ A, const float* __restrict__ B,
    const float* __restrict__ bias, float* __restrict__ C)
{
    __shared__ uint32_t As[128][36];   // [m][k], BK=32 + pad 4
    __shared__ uint32_t Bs[32][136];   // [k][n], BN=128 + pad 8

    const int tid  = threadIdx.x;
    const int lane = tid & 31;
    const int wid  = tid >> 5;
    const int g    = lane >> 2;
    const int t    = lane & 3;
    const int wm   = wid >> 1;
    const int wn   = wid & 1;

    const int bm = blockIdx.y * 128;
    const int bn = blockIdx.x * 128;

    float acc[2][8][4];
#pragma unroll
    for (int mt = 0; mt < 2; mt++)
#pragma unroll
        for (int nt = 0; nt < 8; nt++)
#pragma unroll
            for (int r = 0; r < 4; r++) acc[mt][nt][r] = 0.0f;

    float4 sa[4], sb[4];

#pragma unroll
    for (int i = 0; i < 4; i++) {
        int slot = i * 256 + tid;
        int ar = slot >> 3, ac4 = slot & 7;
        sa[i] = *(const float4*)&A[(size_t)(bm + ar) * GK + ac4 * 4];
        int br = slot >> 5, bc4 = slot & 31;
        sb[i] = *(const float4*)&B[(size_t)br * N + bn + bc4 * 4];
    }

    for (int it = 0; it < GNT; it++) {
#pragma unroll
        for (int i = 0; i < 4; i++) {
            int slot = i * 256 + tid;
            int ar = slot >> 3, ac4 = slot & 7;
            uint4 av = make_uint4(f2tf32(sa[i].x), f2tf32(sa[i].y),
                                  f2tf32(sa[i].z), f2tf32(sa[i].w));
            *(uint4*)&As[ar][ac4 * 4] = av;
            int br = slot >> 5, bc4 = slot & 31;
            uint4 bv = make_uint4(f2tf32(sb[i].x), f2tf32(sb[i].y),
                                  f2tf32(sb[i].z), f2tf32(sb[i].w));
            *(uint4*)&Bs[br][bc4 * 4] = bv;
        }
        __syncthreads();

        if (it + 1 < GNT) {
            const int k0 = (it + 1) * 32;
#pragma unroll
            for (int i = 0; i < 4; i++) {
                int slot = i * 256 + tid;
                int ar = slot >> 3, ac4 = slot & 7;
                sa[i] = *(const float4*)&A[(size_t)(bm + ar) * GK + k0 + ac4 * 4];
                int br = slot >> 5, bc4 = slot & 31;
                sb[i] = *(const float4*)&B[(size_t)(k0 + br) * N + bn + bc4 * 4];
            }
        }

#pragma unroll
        for (int ks = 0; ks < 4; ks++) {
            const int kb = ks * 8;
            uint32_t af[2][4];
#pragma unroll
            for (int mt = 0; mt < 2; mt++) {
                const int mb = wm * 32 + mt * 16;
                af[mt][0] = As[mb + g    ][kb + t    ];
                af[mt][1] = As[mb + g + 8][kb + t    ];
                af[mt][2] = As[mb + g    ][kb + t + 4];
                af[mt][3] = As[mb + g + 8][kb + t + 4];
            }
            uint32_t bf[8][2];
#pragma unroll
            for (int nt = 0; nt < 8; nt++) {
                const int nb = wn * 64 + nt * 8 + g;
                bf[nt][0] = Bs[kb + t    ][nb];
                bf[nt][1] = Bs[kb + t + 4][nb];
            }
#pragma unroll
            for (int mt = 0; mt < 2; mt++)
#pragma unroll
                for (int nt = 0; nt < 8; nt++)
                    mma_tf32(acc[mt][nt], af[mt], bf[nt]);
        }
        __syncthreads();
    }

#pragma unroll
    for (int mt = 0; mt < 2; mt++) {
        const int row0 = bm + wm * 32 + mt * 16 + g;
#pragma unroll
        for (int nt = 0; nt < 8; nt++) {
            const int col = bn + wn * 64 + nt * 8 + 2 * t;
            const float b0 = bias[col], b1 = bias[col + 1];
            float2 v0 = make_float2(acc[mt][nt][0] + b0, acc[mt][nt][1] + b1);
            float2 v1 = make_float2(acc[mt][nt][2] + b0, acc[mt][nt][3] + b1);
            *(float2*)&C[(size_t)row0 * N + col]       = v0;
            *(float2*)&C[(size_t)(row0 + 8) * N + col] = v1;
        }
    }
}

__global__ __launch_bounds__(256) void qkv_gemm(
    const float* __restrict__ x, const float* __restrict__ Wqkv,
    const float* __restrict__ bqkv)
{
    tf32_gemm_body(QKV_N, x, Wqkv, bqkv, g_qkv);
}

__global__ __launch_bounds__(256) void out_gemm(
    const float* __restrict__ Wout, const float* __restrict__ bout,
    float* __restrict__ out)
{
    tf32_gemm_body(EE, g_attn, Wout, bout, out);
}

// ---------------------------------------------------------------------------
// Tensor-core flash attention (tf32 MMA for QK^T and PV).
// grid (S/64, B*H), 128 threads = 4 warps; warp w owns q rows [w*16, w*16+16).
// Q tile held in registers as A-fragments (constant across K loop).
// Per 64-key tile: QK^T (64 MMA/warp) -> online softmax (quad shfl reductions,
// branchless alpha-rescale, base-2 logits) -> P via smem (reuses Ks buffer;
// accumulator layout != A-frag layout) -> PV (64 MMA/warp).
// Smem stride 68: (8n+g)*68 + t == 4g + t (mod 32) -> conflict-free frag LDS.
// ---------------------------------------------------------------------------
__global__ __launch_bounds__(128) void flash_attn(const int* __restrict__ mask)
{
    __shared__ uint32_t Ks[64][68];   // K tile (tf32) / reused as P tile
    __shared__ uint32_t Vs[64][68];   // V tile (tf32)
    __shared__ float msk[64];

    const int tid  = threadIdx.x;
    const int lane = tid & 31;
    const int wid  = tid >> 5;
    const int g    = lane >> 2;       // groupID (row within 8)
    const int t    = lane & 3;        // threadID_in_group
    const int b    = blockIdx.y / HH;
    const int h    = blockIdx.y % HH;
    const int q0   = blockIdx.x * 64;
    const int wrow = wid * 16;        // warp's row base within the 64-row tile

    const float QSCALE = 0.125f * 1.4426950408889634f;  // 1/sqrt(D) * log2(e)

    // ---- stage Q tile (scaled, tf32) into Ks, then read A-fragments ----
#pragma unroll
    for (int i = 0; i < 8; i++) {
        int slot = i * 128 + tid;          // [0,1024) float4 slots
        int rr = slot >> 4, c4 = slot & 15;
        float4 v = *(const float4*)
            &g_qkv[(size_t)(b * SS + q0 + rr) * QKV_N + h * DD + c4 * 4];
        uint4 u = make_uint4(f2tf32(v.x * QSCALE), f2tf32(v.y * QSCALE),
                             f2tf32(v.z * QSCALE), f2tf32(v.w * QSCALE));
        *(uint4*)&Ks[rr][c4 * 4] = u;
    }
    __syncthreads();

    uint32_t aq[8][4];
#pragma unroll
    for (int ks = 0; ks < 8; ks++) {
        const int kb = ks * 8;
        aq[ks][0] = Ks[wrow + g    ][kb + t    ];
        aq[ks][1] = Ks[wrow + g + 8][kb + t    ];
        aq[ks][2] = Ks[wrow + g    ][kb + t + 4];
        aq[ks][3] = Ks[wrow + g + 8][kb + t + 4];
    }

    float o[8][4];
#pragma unroll
    for (int nt = 0; nt < 8; nt++)
#pragma unroll
        for (int r = 0; r < 4; r++) o[nt][r] = 0.0f;
    float m0 = -1e4f, m1 = -1e4f;    // -1e4 (not -1e30): keeps fully-masked
    float l0 = 0.0f,  l1 = 0.0f;     // tiles from producing p==1 artifacts

    for (int kt = 0; kt < SS / 64; kt++) {
        __syncthreads();   // Q frags read / prev-tile Ps,Vs consumed

        // ---- load K,V tiles (tf32) ----
#pragma unroll
        for (int i = 0; i < 8; i++) {
            int slot = i * 128 + tid;
            int rr = slot >> 4, c4 = slot & 15;
            size_t base = (size_t)(b * SS + kt * 64 + rr) * QKV_N + h * DD;
            float4 kv = *(const float4*)&g_qkv[base + EE + c4 * 4];
            float4 vv = *(const float4*)&g_qkv[base + 2 * EE + c4 * 4];
            *(uint4*)&Ks[rr][c4 * 4] = make_uint4(f2tf32(kv.x), f2tf32(kv.y),
                                                  f2tf32(kv.z), f2tf32(kv.w));
            *(uint4*)&Vs[rr][c4 * 4] = make_uint4(f2tf32(vv.x), f2tf32(vv.y),
                                                  f2tf32(vv.z), f2tf32(vv.w));
        }
        if (tid < 64)
            msk[tid] = (mask[b * SS + kt * 64 + tid] == 0) ? -1e30f : 0.0f;
        __syncthreads();

        // ---- QK^T: s[nt] = Q(16xD) @ K^T(Dx64) ----
        float s[8][4];
#pragma unroll
        for (int nt = 0; nt < 8; nt++)
#pragma unroll
            for (int r = 0; r < 4; r++) s[nt][r] = 0.0f;
#pragma unroll
        for (int ks = 0; ks < 8; ks++) {
            const int kb = ks * 8;
            uint32_t bf[8][2];
#pragma unroll
            for (int nt = 0; nt < 8; nt++) {
                bf[nt][0] = Ks[nt * 8 + g][kb + t    ];
                bf[nt][1] = Ks[nt * 8 + g][kb + t + 4];
            }
#pragma unroll
            for (int nt = 0; nt < 8; nt++)
                mma_tf32(s[nt], aq[ks], bf[nt]);
        }
        __syncthreads();   // all warps done reading Ks before P overwrite

        // ---- mask + online softmax (rows g and g+8 of warp tile) ----
        float r0 = -1e30f, r1 = -1e30f;
#pragma unroll
        for (int nt = 0; nt < 8; nt++) {
            float mk0 = msk[nt * 8 + 2 * t];
            float mk1 = msk[nt * 8 + 2 * t + 1];
            s[nt][0] += mk0; s[nt][1] += mk1;
            s[nt][2] += mk0; s[nt][3] += mk1;
            r0 = fmaxf(r0, fmaxf(s[nt][0], s[nt][1]));
            r1 = fmaxf(r1, fmaxf(s[nt][2], s[nt][3]));
        }
        r0 = fmaxf(r0, __shfl_xor_sync(0xffffffff, r0, 1));
        r0 = fmaxf(r0, __shfl_xor_sync(0xffffffff, r0, 2));
        r1 = fmaxf(r1, __shfl_xor_sync(0xffffffff, r1, 1));
        r1 = fmaxf(r1, __shfl_xor_sync(0xffffffff, r1, 2));

        float mn0 = fmaxf(m0, r0), mn1 = fmaxf(m1, r1);
        float a0 = ex2(m0 - mn0), a1 = ex2(m1 - mn1);
        m0 = mn0; m1 = mn1;

        float p0 = 0.f, p1 = 0.f;
#pragma unroll
        for (int nt = 0; nt < 8; nt++) {
            s[nt][0] = ex2(s[nt][0] - mn0);
            s[nt][1] = ex2(s[nt][1] - mn0);
            s[nt][2] = ex2(s[nt][2] - mn1);
            s[nt][3] = ex2(s[nt][3] - mn1);
            p0 += s[nt][0] + s[nt][1];
            p1 += s[nt][2] + s[nt][3];
        }
        p0 += __shfl_xor_sync(0xffffffff, p0, 1);
        p0 += __shfl_xor_sync(0xffffffff, p0, 2);
        p1 += __shfl_xor_sync(0xffffffff, p1, 1);
        p1 += __shfl_xor_sync(0xffffffff, p1, 2);
        l0 = l0 * a0 + p0;
        l1 = l1 * a1 + p1;

#pragma unroll
        for (int nt = 0; nt < 8; nt++) {
            o[nt][0] *= a0; o[nt][1] *= a0;
            o[nt][2] *= a1; o[nt][3] *= a1;
        }

        // ---- store P (tf32) into Ks region; warp-local rows ----
#pragma unroll
        for (int nt = 0; nt < 8; nt++) {
            const int col = nt * 8 + 2 * t;
            *(uint2*)&Ks[wrow + g    ][col] =
                make_uint2(f2tf32(s[nt][0]), f2tf32(s[nt][1]));
            *(uint2*)&Ks[wrow + g + 8][col] =
                make_uint2(f2tf32(s[nt][2]), f2tf32(s[nt][3]));
        }
        __syncwarp();

        // ---- PV: o += P(16x64) @ V(64x64) ----
#pragma unroll
        for (int ks = 0; ks < 8; ks++) {
            const int kb = ks * 8;
            uint32_t ap[4];
            ap[0] = Ks[wrow + g    ][kb + t    ];
            ap[1] = Ks[wrow + g + 8][kb + t    ];
            ap[2] = Ks[wrow + g    ][kb + t + 4];
            ap[3] = Ks[wrow + g + 8][kb + t + 4];
            uint32_t bv[8][2];
#pragma unroll
            for (int nt = 0; nt < 8; nt++) {
                bv[nt][0] = Vs[kb + t    ][nt * 8 + g];
                bv[nt][1] = Vs[kb + t + 4][nt * 8 + g];
            }
#pragma unroll
            for (int nt = 0; nt < 8; nt++)
                mma_tf32(o[nt], ap, bv[nt]);
        }
    }

    // ---- normalize + write ----
    const float inv0 = 1.0f / l0, inv1 = 1.0f / l1;
    const int row0 = b * SS + q0 + wrow + g;
#pragma unroll
    for (int nt = 0; nt < 8; nt++) {
        const int col = h * DD + nt * 8 + 2 * t;
        *(float2*)&g_attn[(size_t)row0 * EE + col] =
            make_float2(o[nt][0] * inv0, o[nt][1] * inv0);
        *(float2*)&g_attn[(size_t)(row0 + 8) * EE + col] =
            make_float2(o[nt][2] * inv1, o[nt][3] * inv1);
    }
}

// ---------------------------------------------------------------------------
// Launch — pure kernel launches only (graph-capture safe).
// ---------------------------------------------------------------------------
extern "C" void kernel_launch(void* const* d_in, const int* in_sizes, int n_in,
                              void* d_out, int out_size)
{
    const float* x    = (const float*)d_in[0];
    const int*   mask = (const int*)d_in[1];
    const float* Wqkv = (const float*)d_in[2];
    const float* bqkv = (const float*)d_in[3];
    const float* Wout = (const float*)d_in[4];
    const float* bout = (const float*)d_in[5];
    float* out = (float*)d_out;

    {   // 1) qkv = x @ Wqkv + bqkv
        dim3 grid(QKV_N / 128, ROWS / 128);
        qkv_gemm<<<grid, 256>>>(x, Wqkv, bqkv);
    }
    {   // 2) attention -> g_attn
        dim3 grid(SS / 64, BB * HH);
        flash_attn<<<grid, 128>>>(mask);
    }
    {   // 3) out = g_attn @ Wout + bout
        dim3 grid(EE / 128, ROWS / 128);
        out_gemm<<<grid, 256>>>(Wout, bout, out);
    }
}

// round 10
// speedup vs baseline: 5.0288x; 1.0709x over previous
#include <cuda_runtime.h>
#include <cuda_bf16.h>
#include <cstdint>

// Problem constants
#define BB 2
#define SS 2048
#define EE 1024
#define HH 16
#define DD 64
#define ROWS (BB * SS)        // 4096
#define QKV_N (3 * EE)        // 3072

// Scratch (device globals — no allocation allowed).
__device__ float g_qkv[ROWS * QKV_N];   // [4096, 3072]  (q | k | v per row)
__device__ float g_attn[ROWS * EE];     // [4096, 1024]  attention output

// -------------------------------------------------------------------------
// helpers
// -------------------------------------------------------------------------
__device__ __forceinline__ uint32_t f2tf32(float x) {
    uint32_t r;
    asm("cvt.rna.tf32.f32 %0, %1;" : "=r"(r) : "f"(x));
    return r;
}
__device__ __forceinline__ uint32_t u2tf32(uint32_t xb) {
    uint32_t r;
    asm("cvt.rna.tf32.f32 %0, %1;" : "=r"(r) : "f"(__uint_as_float(xb)));
    return r;
}
__device__ __forceinline__ float ex2(float x) {
    float r;
    asm("ex2.approx.f32 %0, %1;" : "=f"(r) : "f"(x));
    return r;
}
__device__ __forceinline__ void cp_async16(void* smem_dst, const void* gmem_src) {
    uint32_t dst = (uint32_t)__cvta_generic_to_shared(smem_dst);
    asm volatile("cp.async.cg.shared.global [%0], [%1], 16;\n"
                 :: "r"(dst), "l"(gmem_src));
}
__device__ __forceinline__ void cp_async_commit() {
    asm volatile("cp.async.commit_group;\n");
}
template <int N>
__device__ __forceinline__ void cp_async_wait() {
    asm volatile("cp.async.wait_group %0;\n" :: "n"(N));
}

// mma.sync m16n8k8 tf32: D = A(16x8,row) * B(8x8,col-frag) + D
__device__ __forceinline__ void mma_tf32(float c[4], const uint32_t a[4],
                                         const uint32_t b[2]) {
    asm volatile(
        "mma.sync.aligned.m16n8k8.row.col.f32.tf32.tf32.f32 "
        "{%0,%1,%2,%3}, {%4,%5,%6,%7}, {%8,%9}, {%0,%1,%2,%3};"
        : "+f"(c[0]), "+f"(c[1]), "+f"(c[2]), "+f"(c[3])
        : "r"(a[0]), "r"(a[1]), "r"(a[2]), "r"(a[3]),
          "r"(b[0]), "r"(b[1]));
}

// ---------------------------------------------------------------------------
// TF32 tensor-core GEMM, cp.async + double-buffered smem.
// C[M,N] = A[M,K] @ B[K,N] + bias[N]
// BM=BN=128, BK=16, 256 threads = 8 warps (4 m x 2 n), warp tile 32x64.
// fp32 lands in smem raw; tf32 rounding (rna) applied in the fragment path.
// Bank math: A banks = (20g+t) mod 32 = 4g+t distinct; B banks = 8t+g distinct.
// ---------------------------------------------------------------------------
#define GK 1024
#define GNT (GK / 16)   // 64 K-iterations

__device__ __forceinline__ void tf32_gemm_body(
    int N,
    const float* __restrict__ A, const float* __restrict__ B,
    const float* __restrict__ bias, float* __restrict__ C)
{
    __shared__ uint32_t As[2][128][20];   // [m][k], BK=16 + pad 4
    __shared__ uint32_t Bs[2][16][136];   // [k][n], BN=128 + pad 8

    const int tid  = threadIdx.x;
    const int lane = tid & 31;
    const int wid  = tid >> 5;
    const int g    = lane >> 2;
    const int t    = lane & 3;
    const int wm   = wid >> 1;
    const int wn   = wid & 1;

    const int bm = blockIdx.y * 128;
    const int bn = blockIdx.x * 128;

    float acc[2][8][4];
#pragma unroll
    for (int mt = 0; mt < 2; mt++)
#pragma unroll
        for (int nt = 0; nt < 8; nt++)
#pragma unroll
            for (int r = 0; r < 4; r++) acc[mt][nt][r] = 0.0f;

    // Per-thread cp.async slots: A tile 128x16 = 512 chunks -> 2/thread,
    //                            B tile  16x128 = 512 chunks -> 2/thread.
    const int a_r0 = tid >> 2,          a_c0 = (tid & 3) * 4;        // slot tid
    const int a_r1 = (256 + tid) >> 2,  a_c1 = a_c0;                  // slot tid+256
    const int b_r0 = tid >> 5,          b_c0 = (tid & 31) * 4;
    const int b_r1 = ((256 + tid) >> 5), b_c1 = b_c0;

    // ---- prologue: tile 0 -> buf 0 ----
    cp_async16(&As[0][a_r0][a_c0], &A[(size_t)(bm + a_r0) * GK + a_c0]);
    cp_async16(&As[0][a_r1][a_c1], &A[(size_t)(bm + a_r1) * GK + a_c1]);
    cp_async16(&Bs[0][b_r0][b_c0], &B[(size_t)b_r0 * N + bn + b_c0]);
    cp_async16(&Bs[0][b_r1][b_c1], &B[(size_t)b_r1 * N + bn + b_c1]);
    cp_async_commit();

    for (int it = 0; it < GNT; it++) {
        const int cur = it & 1;

        if (it + 1 < GNT) {
            const int k0 = (it + 1) * 16;
            cp_async16(&As[cur ^ 1][a_r0][a_c0],
                       &A[(size_t)(bm + a_r0) * GK + k0 + a_c0]);
            cp_async16(&As[cur ^ 1][a_r1][a_c1],
                       &A[(size_t)(bm + a_r1) * GK + k0 + a_c1]);
            cp_async16(&Bs[cur ^ 1][b_r0][b_c0],
                       &B[(size_t)(k0 + b_r0) * N + bn + b_c0]);
            cp_async16(&Bs[cur ^ 1][b_r1][b_c1],
                       &B[(size_t)(k0 + b_r1) * N + bn + b_c1]);
            cp_async_commit();
            cp_async_wait<1>();    // tile `it` complete; next may stay in flight
        } else {
            cp_async_wait<0>();
        }
        __syncthreads();

        // ---- compute on buf cur: 2 k-steps of 8 ----
#pragma unroll
        for (int ks = 0; ks < 2; ks++) {
            const int kb = ks * 8;
            uint32_t af[2][4];
#pragma unroll
            for (int mt = 0; mt < 2; mt++) {
                const int mb = wm * 32 + mt * 16;
                af[mt][0] = u2tf32(As[cur][mb + g    ][kb + t    ]);
                af[mt][1] = u2tf32(As[cur][mb + g + 8][kb + t    ]);
                af[mt][2] = u2tf32(As[cur][mb + g    ][kb + t + 4]);
                af[mt][3] = u2tf32(As[cur][mb + g + 8][kb + t + 4]);
            }
            uint32_t bf[8][2];
#pragma unroll
            for (int nt = 0; nt < 8; nt++) {
                const int nb = wn * 64 + nt * 8 + g;
                bf[nt][0] = u2tf32(Bs[cur][kb + t    ][nb]);
                bf[nt][1] = u2tf32(Bs[cur][kb + t + 4][nb]);
            }
#pragma unroll
            for (int mt = 0; mt < 2; mt++)
#pragma unroll
                for (int nt = 0; nt < 8; nt++)
                    mma_tf32(acc[mt][nt], af[mt], bf[nt]);
        }
        __syncthreads();   // all reads of buf cur done before it is refilled
    }

    // ---- epilogue: bias + store ----
#pragma unroll
    for (int mt = 0; mt < 2; mt++) {
        const int row0 = bm + wm * 32 + mt * 16 + g;
#pragma unroll
        for (int nt = 0; nt < 8; nt++) {
            const int col = bn + wn * 64 + nt * 8 + 2 * t;
            const float b0 = bias[col], b1 = bias[col + 1];
            float2 v0 = make_float2(acc[mt][nt][0] + b0, acc[mt][nt][1] + b1);
            float2 v1 = make_float2(acc[mt][nt][2] + b0, acc[mt][nt][3] + b1);
            *(float2*)&C[(size_t)row0 * N + col]       = v0;
            *(float2*)&C[(size_t)(row0 + 8) * N + col] = v1;
        }
    }
}

__global__ __launch_bounds__(256) void qkv_gemm(
    const float* __restrict__ x, const float* __restrict__ Wqkv,
    const float* __restrict__ bqkv)
{
    tf32_gemm_body(QKV_N, x, Wqkv, bqkv, g_qkv);
}

__global__ __launch_bounds__(256) void out_gemm(
    const float* __restrict__ Wout, const float* __restrict__ bout,
    float* __restrict__ out)
{
    tf32_gemm_body(EE, g_attn, Wout, bout, out);
}

// ---------------------------------------------------------------------------
// Tensor-core flash attention (tf32 MMA) — EXACT round-9 version (proven).
// grid (S/64, B*H), 128 threads = 4 warps; warp w owns q rows [w*16, w*16+16).
// ---------------------------------------------------------------------------
__global__ __launch_bounds__(128) void flash_attn(const int* __restrict__ mask)
{
    __shared__ uint32_t Ks[64][68];   // K tile (tf32) / reused as P tile
    __shared__ uint32_t Vs[64][68];   // V tile (tf32)
    __shared__ float msk[64];

    const int tid  = threadIdx.x;
    const int lane = tid & 31;
    const int wid  = tid >> 5;
    const int g    = lane >> 2;
    const int t    = lane & 3;
    const int b    = blockIdx.y / HH;
    const int h    = blockIdx.y % HH;
    const int q0   = blockIdx.x * 64;
    const int wrow = wid * 16;

    const float QSCALE = 0.125f * 1.4426950408889634f;  // 1/sqrt(D) * log2(e)

    // ---- stage Q tile (scaled, tf32) into Ks, then read A-fragments ----
#pragma unroll
    for (int i = 0; i < 8; i++) {
        int slot = i * 128 + tid;
        int rr = slot >> 4, c4 = slot & 15;
        float4 v = *(const float4*)
            &g_qkv[(size_t)(b * SS + q0 + rr) * QKV_N + h * DD + c4 * 4];
        uint4 u = make_uint4(f2tf32(v.x * QSCALE), f2tf32(v.y * QSCALE),
                             f2tf32(v.z * QSCALE), f2tf32(v.w * QSCALE));
        *(uint4*)&Ks[rr][c4 * 4] = u;
    }
    __syncthreads();

    uint32_t aq[8][4];
#pragma unroll
    for (int ks = 0; ks < 8; ks++) {
        const int kb = ks * 8;
        aq[ks][0] = Ks[wrow + g    ][kb + t    ];
        aq[ks][1] = Ks[wrow + g + 8][kb + t    ];
        aq[ks][2] = Ks[wrow + g    ][kb + t + 4];
        aq[ks][3] = Ks[wrow + g + 8][kb + t + 4];
    }

    float o[8][4];
#pragma unroll
    for (int nt = 0; nt < 8; nt++)
#pragma unroll
        for (int r = 0; r < 4; r++) o[nt][r] = 0.0f;
    float m0 = -1e4f, m1 = -1e4f;
    float l0 = 0.0f,  l1 = 0.0f;

    for (int kt = 0; kt < SS / 64; kt++) {
        __syncthreads();

        // ---- load K,V tiles (tf32) ----
#pragma unroll
        for (int i = 0; i < 8; i++) {
            int slot = i * 128 + tid;
            int rr = slot >> 4, c4 = slot & 15;
            size_t base = (size_t)(b * SS + kt * 64 + rr) * QKV_N + h * DD;
            float4 kv = *(const float4*)&g_qkv[base + EE + c4 * 4];
            float4 vv = *(const float4*)&g_qkv[base + 2 * EE + c4 * 4];
            *(uint4*)&Ks[rr][c4 * 4] = make_uint4(f2tf32(kv.x), f2tf32(kv.y),
                                                  f2tf32(kv.z), f2tf32(kv.w));
            *(uint4*)&Vs[rr][c4 * 4] = make_uint4(f2tf32(vv.x), f2tf32(vv.y),
                                                  f2tf32(vv.z), f2tf32(vv.w));
        }
        if (tid < 64)
            msk[tid] = (mask[b * SS + kt * 64 + tid] == 0) ? -1e30f : 0.0f;
        __syncthreads();

        // ---- QK^T ----
        float s[8][4];
#pragma unroll
        for (int nt = 0; nt < 8; nt++)
#pragma unroll
            for (int r = 0; r < 4; r++) s[nt][r] = 0.0f;
#pragma unroll
        for (int ks = 0; ks < 8; ks++) {
            const int kb = ks * 8;
            uint32_t bf[8][2];
#pragma unroll
            for (int nt = 0; nt < 8; nt++) {
                bf[nt][0] = Ks[nt * 8 + g][kb + t    ];
                bf[nt][1] = Ks[nt * 8 + g][kb + t + 4];
            }
#pragma unroll
            for (int nt = 0; nt < 8; nt++)
                mma_tf32(s[nt], aq[ks], bf[nt]);
        }
        __syncthreads();

        // ---- mask + online softmax ----
        float r0 = -1e30f, r1 = -1e30f;
#pragma unroll
        for (int nt = 0; nt < 8; nt++) {
            float mk0 = msk[nt * 8 + 2 * t];
            float mk1 = msk[nt * 8 + 2 * t + 1];
            s[nt][0] += mk0; s[nt][1] += mk1;
            s[nt][2] += mk0; s[nt][3] += mk1;
            r0 = fmaxf(r0, fmaxf(s[nt][0], s[nt][1]));
            r1 = fmaxf(r1, fmaxf(s[nt][2], s[nt][3]));
        }
        r0 = fmaxf(r0, __shfl_xor_sync(0xffffffff, r0, 1));
        r0 = fmaxf(r0, __shfl_xor_sync(0xffffffff, r0, 2));
        r1 = fmaxf(r1, __shfl_xor_sync(0xffffffff, r1, 1));
        r1 = fmaxf(r1, __shfl_xor_sync(0xffffffff, r1, 2));

        float mn0 = fmaxf(m0, r0), mn1 = fmaxf(m1, r1);
        float a0 = ex2(m0 - mn0), a1 = ex2(m1 - mn1);
        m0 = mn0; m1 = mn1;

        float p0 = 0.f, p1 = 0.f;
#pragma unroll
        for (int nt = 0; nt < 8; nt++) {
            s[nt][0] = ex2(s[nt][0] - mn0);
            s[nt][1] = ex2(s[nt][1] - mn0);
            s[nt][2] = ex2(s[nt][2] - mn1);
            s[nt][3] = ex2(s[nt][3] - mn1);
            p0 += s[nt][0] + s[nt][1];
            p1 += s[nt][2] + s[nt][3];
        }
        p0 += __shfl_xor_sync(0xffffffff, p0, 1);
        p0 += __shfl_xor_sync(0xffffffff, p0, 2);
        p1 += __shfl_xor_sync(0xffffffff, p1, 1);
        p1 += __shfl_xor_sync(0xffffffff, p1, 2);
        l0 = l0 * a0 + p0;
        l1 = l1 * a1 + p1;

#pragma unroll
        for (int nt = 0; nt < 8; nt++) {
            o[nt][0] *= a0; o[nt][1] *= a0;
            o[nt][2] *= a1; o[nt][3] *= a1;
        }

        // ---- store P (tf32) into Ks region ----
#pragma unroll
        for (int nt = 0; nt < 8; nt++) {
            const int col = nt * 8 + 2 * t;
            *(uint2*)&Ks[wrow + g    ][col] =
                make_uint2(f2tf32(s[nt][0]), f2tf32(s[nt][1]));
            *(uint2*)&Ks[wrow + g + 8][col] =
                make_uint2(f2tf32(s[nt][2]), f2tf32(s[nt][3]));
        }
        __syncwarp();

        // ---- PV ----
#pragma unroll
        for (int ks = 0; ks < 8; ks++) {
            const int kb = ks * 8;
            uint32_t ap[4];
            ap[0] = Ks[wrow + g    ][kb + t    ];
            ap[1] = Ks[wrow + g + 8][kb + t    ];
            ap[2] = Ks[wrow + g    ][kb + t + 4];
            ap[3] = Ks[wrow + g + 8][kb + t + 4];
            uint32_t bv[8][2];
#pragma unroll
            for (int nt = 0; nt < 8; nt++) {
                bv[nt][0] = Vs[kb + t    ][nt * 8 + g];
                bv[nt][1] = Vs[kb + t + 4][nt * 8 + g];
            }
#pragma unroll
            for (int nt = 0; nt < 8; nt++)
                mma_tf32(o[nt], ap, bv[nt]);
        }
    }

    // ---- normalize + write ----
    const float inv0 = 1.0f / l0, inv1 = 1.0f / l1;
    const int row0 = b * SS + q0 + wrow + g;
#pragma unroll
    for (int nt = 0; nt < 8; nt++) {
        const int col = h * DD + nt * 8 + 2 * t;
        *(float2*)&g_attn[(size_t)row0 * EE + col] =
            make_float2(o[nt][0] * inv0, o[nt][1] * inv0);
        *(float2*)&g_attn[(size_t)(row0 + 8) * EE + col] =
            make_float2(o[nt][2] * inv1, o[nt][3] * inv1);
    }
}

// ---------------------------------------------------------------------------
// Launch — pure kernel launches only (graph-capture safe).
// ---------------------------------------------------------------------------
extern "C" void kernel_launch(void* const* d_in, const int* in_sizes, int n_in,
                              void* d_out, int out_size)
{
    const float* x    = (const float*)d_in[0];
    const int*   mask = (const int*)d_in[1];
    const float* Wqkv = (const float*)d_in[2];
    const float* bqkv = (const float*)d_in[3];
    const float* Wout = (const float*)d_in[4];
    const float* bout = (const float*)d_in[5];
    float* out = (float*)d_out;

    {   // 1) qkv = x @ Wqkv + bqkv
        dim3 grid(QKV_N / 128, ROWS / 128);
        qkv_gemm<<<grid, 256>>>(x, Wqkv, bqkv);
    }
    {   // 2) attention -> g_attn
        dim3 grid(SS / 64, BB * HH);
        flash_attn<<<grid, 128>>>(mask);
    }
    {   // 3) out = g_attn @ Wout + bout
        dim3 grid(EE / 128, ROWS / 128);
        out_gemm<<<grid, 256>>>(Wout, bout, out);
    }
}

// round 11
// speedup vs baseline: 5.2642x; 1.0468x over previous
#include <cuda_runtime.h>
#include <cuda_bf16.h>
#include <cstdint>

// Problem constants
#define BB 2
#define SS 2048
#define EE 1024
#define HH 16
#define DD 64
#define ROWS (BB * SS)        // 4096
#define QKV_N (3 * EE)        // 3072

// Scratch (device globals — no allocation allowed).
__device__ float g_qkv[ROWS * QKV_N];   // [4096, 3072] qkv, tf32-rounded
__device__ float g_attn[ROWS * EE];     // [4096, 1024] attn out, tf32-rounded
__device__ float g_xt[ROWS * EE];       // x, tf32-rounded
__device__ float g_wq[EE * QKV_N];      // Wqkv, tf32-rounded
__device__ float g_wo[EE * EE];         // Wout, tf32-rounded

// -------------------------------------------------------------------------
// helpers
// -------------------------------------------------------------------------
__device__ __forceinline__ uint32_t f2tf32(float x) {
    uint32_t r;
    asm("cvt.rna.tf32.f32 %0, %1;" : "=r"(r) : "f"(x));
    return r;
}
__device__ __forceinline__ float f2tf32f(float x) {
    return __uint_as_float(f2tf32(x));
}
__device__ __forceinline__ float ex2(float x) {
    float r;
    asm("ex2.approx.f32 %0, %1;" : "=f"(r) : "f"(x));
    return r;
}
__device__ __forceinline__ void cp_async16(void* smem_dst, const void* gmem_src) {
    uint32_t dst = (uint32_t)__cvta_generic_to_shared(smem_dst);
    asm volatile("cp.async.cg.shared.global [%0], [%1], 16;\n"
                 :: "r"(dst), "l"(gmem_src));
}
__device__ __forceinline__ void cp_async_commit() {
    asm volatile("cp.async.commit_group;\n");
}
template <int N>
__device__ __forceinline__ void cp_async_wait() {
    asm volatile("cp.async.wait_group %0;\n" :: "n"(N));
}

// mma.sync m16n8k8 tf32: D = A(16x8,row) * B(8x8,col-frag) + D
__device__ __forceinline__ void mma_tf32(float c[4], const uint32_t a[4],
                                         const uint32_t b[2]) {
    asm volatile(
        "mma.sync.aligned.m16n8k8.row.col.f32.tf32.tf32.f32 "
        "{%0,%1,%2,%3}, {%4,%5,%6,%7}, {%8,%9}, {%0,%1,%2,%3};"
        : "+f"(c[0]), "+f"(c[1]), "+f"(c[2]), "+f"(c[3])
        : "r"(a[0]), "r"(a[1]), "r"(a[2]), "r"(a[3]),
          "r"(b[0]), "r"(b[1]));
}

// ---------------------------------------------------------------------------
// Pre-convert fp32 -> tf32-rounded fp32 bit patterns (rna). Grid-stride float4.
// ---------------------------------------------------------------------------
__global__ __launch_bounds__(256) void cvt_tf32(const float* __restrict__ src,
                                                float* __restrict__ dst, int n4)
{
    int i = blockIdx.x * blockDim.x + threadIdx.x;
    int stride = gridDim.x * blockDim.x;
    for (; i < n4; i += stride) {
        float4 v = ((const float4*)src)[i];
        v.x = f2tf32f(v.x); v.y = f2tf32f(v.y);
        v.z = f2tf32f(v.z); v.w = f2tf32f(v.w);
        ((float4*)dst)[i] = v;
    }
}

// ---------------------------------------------------------------------------
// TF32 tensor-core GEMM, cp.async + double-buffered smem. Inputs pre-rounded:
// NO cvt anywhere in the hot loop. C stored tf32-rounded (+fp32 bias).
// BM=BN=128, BK=16, 256 threads = 8 warps (4 m x 2 n), warp tile 32x64.
// Bank math: A banks = 4g+t distinct; B banks = 8t+g distinct.
// ---------------------------------------------------------------------------
#define GK 1024
#define GNT (GK / 16)   // 64 K-iterations

template <bool ROUND_C>
__device__ __forceinline__ void tf32_gemm_body(
    int N,
    const float* __restrict__ A, const float* __restrict__ B,
    const float* __restrict__ bias, float* __restrict__ C)
{
    __shared__ uint32_t As[2][128][20];   // [m][k], BK=16 + pad 4
    __shared__ uint32_t Bs[2][16][136];   // [k][n], BN=128 + pad 8

    const int tid  = threadIdx.x;
    const int lane = tid & 31;
    const int wid  = tid >> 5;
    const int g    = lane >> 2;
    const int t    = lane & 3;
    const int wm   = wid >> 1;
    const int wn   = wid & 1;

    const int bm = blockIdx.y * 128;
    const int bn = blockIdx.x * 128;

    float acc[2][8][4];
#pragma unroll
    for (int mt = 0; mt < 2; mt++)
#pragma unroll
        for (int nt = 0; nt < 8; nt++)
#pragma unroll
            for (int r = 0; r < 4; r++) acc[mt][nt][r] = 0.0f;

    const int a_r0 = tid >> 2,           a_c0 = (tid & 3) * 4;
    const int a_r1 = (256 + tid) >> 2,   a_c1 = a_c0;
    const int b_r0 = tid >> 5,           b_c0 = (tid & 31) * 4;
    const int b_r1 = ((256 + tid) >> 5), b_c1 = b_c0;

    cp_async16(&As[0][a_r0][a_c0], &A[(size_t)(bm + a_r0) * GK + a_c0]);
    cp_async16(&As[0][a_r1][a_c1], &A[(size_t)(bm + a_r1) * GK + a_c1]);
    cp_async16(&Bs[0][b_r0][b_c0], &B[(size_t)b_r0 * N + bn + b_c0]);
    cp_async16(&Bs[0][b_r1][b_c1], &B[(size_t)b_r1 * N + bn + b_c1]);
    cp_async_commit();

    for (int it = 0; it < GNT; it++) {
        const int cur = it & 1;

        if (it + 1 < GNT) {
            const int k0 = (it + 1) * 16;
            cp_async16(&As[cur ^ 1][a_r0][a_c0],
                       &A[(size_t)(bm + a_r0) * GK + k0 + a_c0]);
            cp_async16(&As[cur ^ 1][a_r1][a_c1],
                       &A[(size_t)(bm + a_r1) * GK + k0 + a_c1]);
            cp_async16(&Bs[cur ^ 1][b_r0][b_c0],
                       &B[(size_t)(k0 + b_r0) * N + bn + b_c0]);
            cp_async16(&Bs[cur ^ 1][b_r1][b_c1],
                       &B[(size_t)(k0 + b_r1) * N + bn + b_c1]);
            cp_async_commit();
            cp_async_wait<1>();
        } else {
            cp_async_wait<0>();
        }
        __syncthreads();

#pragma unroll
        for (int ks = 0; ks < 2; ks++) {
            const int kb = ks * 8;
            uint32_t af[2][4];
#pragma unroll
            for (int mt = 0; mt < 2; mt++) {
                const int mb = wm * 32 + mt * 16;
                af[mt][0] = As[cur][mb + g    ][kb + t    ];
                af[mt][1] = As[cur][mb + g + 8][kb + t    ];
                af[mt][2] = As[cur][mb + g    ][kb + t + 4];
                af[mt][3] = As[cur][mb + g + 8][kb + t + 4];
            }
            uint32_t bf[8][2];
#pragma unroll
            for (int nt = 0; nt < 8; nt++) {
                const int nb = wn * 64 + nt * 8 + g;
                bf[nt][0] = Bs[cur][kb + t    ][nb];
                bf[nt][1] = Bs[cur][kb + t + 4][nb];
            }
#pragma unroll
            for (int mt = 0; mt < 2; mt++)
#pragma unroll
                for (int nt = 0; nt < 8; nt++)
                    mma_tf32(acc[mt][nt], af[mt], bf[nt]);
        }
        __syncthreads();
    }

#pragma unroll
    for (int mt = 0; mt < 2; mt++) {
        const int row0 = bm + wm * 32 + mt * 16 + g;
#pragma unroll
        for (int nt = 0; nt < 8; nt++) {
            const int col = bn + wn * 64 + nt * 8 + 2 * t;
            const float b0 = bias[col], b1 = bias[col + 1];
            float2 v0, v1;
            if (ROUND_C) {
                v0 = make_float2(f2tf32f(acc[mt][nt][0] + b0),
                                 f2tf32f(acc[mt][nt][1] + b1));
                v1 = make_float2(f2tf32f(acc[mt][nt][2] + b0),
                                 f2tf32f(acc[mt][nt][3] + b1));
            } else {
                v0 = make_float2(acc[mt][nt][0] + b0, acc[mt][nt][1] + b1);
                v1 = make_float2(acc[mt][nt][2] + b0, acc[mt][nt][3] + b1);
            }
            *(float2*)&C[(size_t)row0 * N + col]       = v0;
            *(float2*)&C[(size_t)(row0 + 8) * N + col] = v1;
        }
    }
}

__global__ __launch_bounds__(256) void qkv_gemm(const float* __restrict__ bqkv)
{
    tf32_gemm_body<true>(QKV_N, g_xt, g_wq, bqkv, g_qkv);
}

__global__ __launch_bounds__(256) void out_gemm(
    const float* __restrict__ bout, float* __restrict__ out)
{
    tf32_gemm_body<false>(EE, g_attn, g_wo, bout, out);
}

// ---------------------------------------------------------------------------
// Tensor-core flash attention (tf32 MMA). g_qkv is pre-rounded tf32, so K/V
// tiles go gmem->smem via cp.async with NO cvt and no register round-trip.
// grid (S/64, B*H), 128 threads = 4 warps; warp w owns q rows [w*16, w*16+16).
// Smem stride 68: conflict-free fragment LDS (4g+t / 8t+g patterns).
// ---------------------------------------------------------------------------
__global__ __launch_bounds__(128) void flash_attn(const int* __restrict__ mask)
{
    __shared__ uint32_t Ks[64][68];   // K tile / reused as P tile
    __shared__ uint32_t Vs[64][68];   // V tile
    __shared__ float msk[64];

    const int tid  = threadIdx.x;
    const int lane = tid & 31;
    const int wid  = tid >> 5;
    const int g    = lane >> 2;
    const int t    = lane & 3;
    const int b    = blockIdx.y / HH;
    const int h    = blockIdx.y % HH;
    const int q0   = blockIdx.x * 64;
    const int wrow = wid * 16;

    const float QSCALE = 0.125f * 1.4426950408889634f;  // 1/sqrt(D) * log2(e)

    // ---- stage Q tile (scaled, re-rounded) into Ks, read A-fragments ----
#pragma unroll
    for (int i = 0; i < 8; i++) {
        int slot = i * 128 + tid;
        int rr = slot >> 4, c4 = slot & 15;
        float4 v = *(const float4*)
            &g_qkv[(size_t)(b * SS + q0 + rr) * QKV_N + h * DD + c4 * 4];
        uint4 u = make_uint4(f2tf32(v.x * QSCALE), f2tf32(v.y * QSCALE),
                             f2tf32(v.z * QSCALE), f2tf32(v.w * QSCALE));
        *(uint4*)&Ks[rr][c4 * 4] = u;
    }
    __syncthreads();

    uint32_t aq[8][4];
#pragma unroll
    for (int ks = 0; ks < 8; ks++) {
        const int kb = ks * 8;
        aq[ks][0] = Ks[wrow + g    ][kb + t    ];
        aq[ks][1] = Ks[wrow + g + 8][kb + t    ];
        aq[ks][2] = Ks[wrow + g    ][kb + t + 4];
        aq[ks][3] = Ks[wrow + g + 8][kb + t + 4];
    }

    float o[8][4];
#pragma unroll
    for (int nt = 0; nt < 8; nt++)
#pragma unroll
        for (int r = 0; r < 4; r++) o[nt][r] = 0.0f;
    float m0 = -1e4f, m1 = -1e4f;
    float l0 = 0.0f,  l1 = 0.0f;

    for (int kt = 0; kt < SS / 64; kt++) {
        __syncthreads();   // prior-tile P/V fully consumed

        // ---- async load K,V tiles (already tf32-rounded in gmem) ----
#pragma unroll
        for (int i = 0; i < 8; i++) {
            int slot = i * 128 + tid;
            int rr = slot >> 4, c4 = slot & 15;
            size_t base = (size_t)(b * SS + kt * 64 + rr) * QKV_N + h * DD;
            cp_async16(&Ks[rr][c4 * 4], &g_qkv[base + EE + c4 * 4]);
            cp_async16(&Vs[rr][c4 * 4], &g_qkv[base + 2 * EE + c4 * 4]);
        }
        cp_async_commit();
        if (tid < 64)
            msk[tid] = (mask[b * SS + kt * 64 + tid] == 0) ? -1e30f : 0.0f;
        cp_async_wait<0>();
        __syncthreads();

        // ---- QK^T ----
        float s[8][4];
#pragma unroll
        for (int nt = 0; nt < 8; nt++)
#pragma unroll
            for (int r = 0; r < 4; r++) s[nt][r] = 0.0f;
#pragma unroll
        for (int ks = 0; ks < 8; ks++) {
            const int kb = ks * 8;
            uint32_t bf[8][2];
#pragma unroll
            for (int nt = 0; nt < 8; nt++) {
                bf[nt][0] = Ks[nt * 8 + g][kb + t    ];
                bf[nt][1] = Ks[nt * 8 + g][kb + t + 4];
            }
#pragma unroll
            for (int nt = 0; nt < 8; nt++)
                mma_tf32(s[nt], aq[ks], bf[nt]);
        }
        __syncthreads();   // all warps done reading Ks before P overwrite

        // ---- mask + online softmax ----
        float r0 = -1e30f, r1 = -1e30f;
#pragma unroll
        for (int nt = 0; nt < 8; nt++) {
            float mk0 = msk[nt * 8 + 2 * t];
            float mk1 = msk[nt * 8 + 2 * t + 1];
            s[nt][0] += mk0; s[nt][1] += mk1;
            s[nt][2] += mk0; s[nt][3] += mk1;
            r0 = fmaxf(r0, fmaxf(s[nt][0], s[nt][1]));
            r1 = fmaxf(r1, fmaxf(s[nt][2], s[nt][3]));
        }
        r0 = fmaxf(r0, __shfl_xor_sync(0xffffffff, r0, 1));
        r0 = fmaxf(r0, __shfl_xor_sync(0xffffffff, r0, 2));
        r1 = fmaxf(r1, __shfl_xor_sync(0xffffffff, r1, 1));
        r1 = fmaxf(r1, __shfl_xor_sync(0xffffffff, r1, 2));

        float mn0 = fmaxf(m0, r0), mn1 = fmaxf(m1, r1);
        float a0 = ex2(m0 - mn0), a1 = ex2(m1 - mn1);
        m0 = mn0; m1 = mn1;

        float p0 = 0.f, p1 = 0.f;
#pragma unroll
        for (int nt = 0; nt < 8; nt++) {
            s[nt][0] = ex2(s[nt][0] - mn0);
            s[nt][1] = ex2(s[nt][1] - mn0);
            s[nt][2] = ex2(s[nt][2] - mn1);
            s[nt][3] = ex2(s[nt][3] - mn1);
            p0 += s[nt][0] + s[nt][1];
            p1 += s[nt][2] + s[nt][3];
        }
        p0 += __shfl_xor_sync(0xffffffff, p0, 1);
        p0 += __shfl_xor_sync(0xffffffff, p0, 2);
        p1 += __shfl_xor_sync(0xffffffff, p1, 1);
        p1 += __shfl_xor_sync(0xffffffff, p1, 2);
        l0 = l0 * a0 + p0;
        l1 = l1 * a1 + p1;

#pragma unroll
        for (int nt = 0; nt < 8; nt++) {
            o[nt][0] *= a0; o[nt][1] *= a0;
            o[nt][2] *= a1; o[nt][3] *= a1;
        }

        // ---- store P (tf32) into Ks region ----
#pragma unroll
        for (int nt = 0; nt < 8; nt++) {
            const int col = nt * 8 + 2 * t;
            *(uint2*)&Ks[wrow + g    ][col] =
                make_uint2(f2tf32(s[nt][0]), f2tf32(s[nt][1]));
            *(uint2*)&Ks[wrow + g + 8][col] =
                make_uint2(f2tf32(s[nt][2]), f2tf32(s[nt][3]));
        }
        __syncwarp();

        // ---- PV ----
#pragma unroll
        for (int ks = 0; ks < 8; ks++) {
            const int kb = ks * 8;
            uint32_t ap[4];
            ap[0] = Ks[wrow + g    ][kb + t    ];
            ap[1] = Ks[wrow + g + 8][kb + t    ];
            ap[2] = Ks[wrow + g    ][kb + t + 4];
            ap[3] = Ks[wrow + g + 8][kb + t + 4];
            uint32_t bv[8][2];
#pragma unroll
            for (int nt = 0; nt < 8; nt++) {
                bv[nt][0] = Vs[kb + t    ][nt * 8 + g];
                bv[nt][1] = Vs[kb + t + 4][nt * 8 + g];
            }
#pragma unroll
            for (int nt = 0; nt < 8; nt++)
                mma_tf32(o[nt], ap, bv[nt]);
        }
    }

    // ---- normalize + write (tf32-rounded: feeds out_gemm directly) ----
    const float inv0 = 1.0f / l0, inv1 = 1.0f / l1;
    const int row0 = b * SS + q0 + wrow + g;
#pragma unroll
    for (int nt = 0; nt < 8; nt++) {
        const int col = h * DD + nt * 8 + 2 * t;
        *(float2*)&g_attn[(size_t)row0 * EE + col] =
            make_float2(f2tf32f(o[nt][0] * inv0), f2tf32f(o[nt][1] * inv0));
        *(float2*)&g_attn[(size_t)(row0 + 8) * EE + col] =
            make_float2(f2tf32f(o[nt][2] * inv1), f2tf32f(o[nt][3] * inv1));
    }
}

// ---------------------------------------------------------------------------
// Launch — pure kernel launches only (graph-capture safe).
// ---------------------------------------------------------------------------
extern "C" void kernel_launch(void* const* d_in, const int* in_sizes, int n_in,
                              void* d_out, int out_size)
{
    const float* x    = (const float*)d_in[0];
    const int*   mask = (const int*)d_in[1];
    const float* Wqkv = (const float*)d_in[2];
    const float* bqkv = (const float*)d_in[3];
    const float* Wout = (const float*)d_in[4];
    const float* bout = (const float*)d_in[5];
    float* out = (float*)d_out;

    float* xt = nullptr; float* wq = nullptr; float* wo = nullptr;
    cudaGetSymbolAddress((void**)&xt, g_xt);
    cudaGetSymbolAddress((void**)&wq, g_wq);
    cudaGetSymbolAddress((void**)&wo, g_wo);

    // 0) pre-round inputs to tf32 storage
    cvt_tf32<<<592, 256>>>(x,    xt, ROWS * EE / 4);
    cvt_tf32<<<592, 256>>>(Wqkv, wq, EE * QKV_N / 4);
    cvt_tf32<<<592, 256>>>(Wout, wo, EE * EE / 4);

    {   // 1) qkv = x @ Wqkv + bqkv   (tf32-rounded output)
        dim3 grid(QKV_N / 128, ROWS / 128);
        qkv_gemm<<<grid, 256>>>(bqkv);
    }
    {   // 2) attention -> g_attn (tf32-rounded output)
        dim3 grid(SS / 64, BB * HH);
        flash_attn<<<grid, 128>>>(mask);
    }
    {   // 3) out = g_attn @ Wout + bout  (fp32 output)
        dim3 grid(EE / 128, ROWS / 128);
        out_gemm<<<grid, 256>>>(bout, out);
    }
}